// round 5
// baseline (speedup 1.0000x reference)
#include <cuda_runtime.h>
#include <math.h>

#define NQ 4
#define NL 3
#define DIM 16

typedef unsigned long long u64;

// 4 tensors T_w[10][10], each value duplicated into both f32x2 lanes.
// Layout: g_Tdup[w*100 + p*10 + q]
__device__ u64 g_Tdup[400];

__device__ __forceinline__ u64 ffma2(u64 a, u64 b, u64 c) {
    u64 d;
    asm("fma.rn.f32x2 %0, %1, %2, %3;" : "=l"(d) : "l"(a), "l"(b), "l"(c));
    return d;
}
__device__ __forceinline__ u64 fmul2(u64 a, u64 b) {
    u64 d;
    asm("mul.rn.f32x2 %0, %1, %2;" : "=l"(d) : "l"(a), "l"(b));
    return d;
}
__device__ __forceinline__ u64 pack2(float lo, float hi) {
    u64 d;
    asm("mov.b64 %0, {%1, %2};" : "=l"(d) : "f"(lo), "f"(hi));
    return d;
}
__device__ __forceinline__ void unpack2(u64 v, float& lo, float& hi) {
    asm("mov.b64 {%0, %1}, %2;" : "=f"(lo), "=f"(hi) : "l"(v));
}

// Symmetric-pair index tables: p -> (a, a') with a <= a'
__device__ __constant__ int c_PA[10] = {0,0,0,0,1,1,1,2,2,3};
__device__ __constant__ int c_PB[10] = {0,1,2,3,1,2,3,2,3,3};

// ---------------------------------------------------------------------------
// Prekernel: simulate the params circuit for the 16 basis states -> U, then
// build A_w = Re(U^H Z_w U) and contract to the 4 10x10 tensors T_w.
// ---------------------------------------------------------------------------
__global__ void precompute_T_kernel(const float* __restrict__ params) {
    __shared__ float Ur[DIM][DIM], Ui[DIM][DIM];
    int t = threadIdx.x;

    if (t < DIM) {
        int j = t;
        float2 a[DIM];
#pragma unroll
        for (int k = 0; k < DIM; k++) a[k] = make_float2(k == j ? 1.0f : 0.0f, 0.0f);

        for (int l = 0; l < NL; l++) {
            for (int w = 0; w < NQ; w++) {
                float ty = 0.5f * params[(l * NQ + w) * 2 + 0];
                float sy, cy;
                sincosf(ty, &sy, &cy);
                int m = 1 << (3 - w);
                for (int i = 0; i < DIM; i++) {
                    if (!(i & m)) {
                        float2 a0 = a[i], a1 = a[i | m];
                        a[i]     = make_float2(cy * a0.x - sy * a1.x, cy * a0.y - sy * a1.y);
                        a[i | m] = make_float2(sy * a0.x + cy * a1.x, sy * a0.y + cy * a1.y);
                    }
                }
                float tz = 0.5f * params[(l * NQ + w) * 2 + 1];
                float sz, cz;
                sincosf(tz, &sz, &cz);
                for (int i = 0; i < DIM; i++) {
                    float2 v = a[i];
                    if (i & m) a[i] = make_float2(cz * v.x - sz * v.y, cz * v.y + sz * v.x);
                    else       a[i] = make_float2(cz * v.x + sz * v.y, cz * v.y - sz * v.x);
                }
            }
            for (int w = 0; w < NQ - 1; w++) {
                int mc = 1 << (3 - w);
                int mt = 1 << (2 - w);
                for (int i = 0; i < DIM; i++) {
                    if ((i & mc) && !(i & mt)) {
                        float2 tmp = a[i];
                        a[i] = a[i | mt];
                        a[i | mt] = tmp;
                    }
                }
            }
        }
#pragma unroll
        for (int i = 0; i < DIM; i++) { Ur[i][j] = a[i].x; Ui[i][j] = a[i].y; }
    }
    __syncthreads();

    // A_w(i,j) = sum_k z_w(k) * (Ur[k][i]Ur[k][j] + Ui[k][i]Ui[k][j])
    for (int e = t; e < 400; e += blockDim.x) {
        int w = e / 100;
        int r = e % 100;
        int p = r / 10, q = r % 10;
        int a = c_PA[p], a2 = c_PB[p];
        int b = c_PA[q], b2 = c_PB[q];

        auto Af = [&](int i, int j) {
            float s = 0.0f;
            for (int k = 0; k < DIM; k++) {
                float z = ((k >> (3 - w)) & 1) ? -1.0f : 1.0f;
                s += z * (Ur[k][i] * Ur[k][j] + Ui[k][i] * Ui[k][j]);
            }
            return s;
        };

        float Tv;
        if (a == a2 && b == b2)      Tv = Af(4 * a + b, 4 * a + b);
        else if (a == a2)            Tv = 2.0f * Af(4 * a + b, 4 * a + b2);
        else if (b == b2)            Tv = 2.0f * Af(4 * a + b, 4 * a2 + b);
        else                         Tv = 2.0f * (Af(4 * a + b, 4 * a2 + b2) +
                                                  Af(4 * a + b2, 4 * a2 + b));
        g_Tdup[e] = pack2(Tv, Tv);
    }
}

// ---------------------------------------------------------------------------
// Main kernel: 2 items per thread, packed across the f32x2 lanes.
//   oa_p = qa_a * qa_a'   (10 symmetric outer products, items A|B packed)
//   ob_q = qb_b * qb_b'
//   ev_w(A,B) = sum_p oa_p (x) ( sum_q T_w[p][q] (x) ob_q )
// 440 ffma2 + 20 mul2 per 2 items; no complex epilogue.
// ---------------------------------------------------------------------------
__global__ __launch_bounds__(256, 3) void vqc_main_kernel(
    const float4* __restrict__ patch, float* __restrict__ out, int n) {
    __shared__ __align__(16) u64 sT[400];

    int t = threadIdx.x;
    for (int i = t; i < 400; i += 256) sT[i] = g_Tdup[i];
    __syncthreads();

    int iA = blockIdx.x * 512 + t;
    int iB = iA + 256;
    bool vA = iA < n, vB = iB < n;
    float4 pA = patch[vA ? iA : 0];
    float4 pB = patch[vB ? iB : 0];

    // Per-item 4-vectors qa (qubits 0,1) and qb (qubits 2,3), packed (A,B).
    u64 qa2[4], qb2[4];
    {
        float sA0, cA0, sA1, cA1, sA2, cA2, sA3, cA3;
        float sB0, cB0, sB1, cB1, sB2, cB2, sB3, cB3;
        __sincosf(0.5f * pA.x, &sA0, &cA0);
        __sincosf(0.5f * pA.y, &sA1, &cA1);
        __sincosf(0.5f * pA.z, &sA2, &cA2);
        __sincosf(0.5f * pA.w, &sA3, &cA3);
        __sincosf(0.5f * pB.x, &sB0, &cB0);
        __sincosf(0.5f * pB.y, &sB1, &cB1);
        __sincosf(0.5f * pB.z, &sB2, &cB2);
        __sincosf(0.5f * pB.w, &sB3, &cB3);
        qa2[0] = pack2(cA0 * cA1, cB0 * cB1);
        qa2[1] = pack2(cA0 * sA1, cB0 * sB1);
        qa2[2] = pack2(sA0 * cA1, sB0 * cB1);
        qa2[3] = pack2(sA0 * sA1, sB0 * sB1);
        qb2[0] = pack2(cA2 * cA3, cB2 * cB3);
        qb2[1] = pack2(cA2 * sA3, cB2 * sB3);
        qb2[2] = pack2(sA2 * cA3, sB2 * cB3);
        qb2[3] = pack2(sA2 * sA3, sB2 * sB3);
    }

    u64 oa[10], ob[10];
#pragma unroll
    for (int p = 0; p < 10; p++) {
        oa[p] = fmul2(qa2[c_PA[p]], qa2[c_PB[p]]);
        ob[p] = fmul2(qb2[c_PA[p]], qb2[c_PB[p]]);
    }

    const ulonglong2* T2 = reinterpret_cast<const ulonglong2*>(sT);

#pragma unroll
    for (int w = 0; w < 4; w++) {
        u64 ev = 0ull;
#pragma unroll
        for (int p = 0; p < 10; p++) {
            u64 y = 0ull;
#pragma unroll
            for (int qq = 0; qq < 5; qq++) {
                ulonglong2 tt = T2[w * 50 + p * 5 + qq];  // broadcast LDS.128
                y = ffma2(tt.x, ob[2 * qq + 0], y);
                y = ffma2(tt.y, ob[2 * qq + 1], y);
            }
            ev = ffma2(oa[p], y, ev);
        }
        float eA, eB;
        unpack2(ev, eA, eB);
        if (vA) out[iA * 4 + w] = eA;
        if (vB) out[iB * 4 + w] = eB;
    }
}

// ---------------------------------------------------------------------------
extern "C" void kernel_launch(void* const* d_in, const int* in_sizes, int n_in,
                              void* d_out, int out_size) {
    const float* patch  = (const float*)d_in[0];   // (B, 4) float32
    const float* params = (const float*)d_in[1];   // (3, 4, 2) float32
    int n = in_sizes[0] / 4;                       // B

    precompute_T_kernel<<<1, 128>>>(params);

    int blocks = (n + 511) / 512;
    vqc_main_kernel<<<blocks, 256>>>(
        (const float4*)patch, (float*)d_out, n);
}

// round 6
// speedup vs baseline: 1.1419x; 1.1419x over previous
#include <cuda_runtime.h>
#include <math.h>

#define NQ 4
#define NL 3
#define DIM 16

typedef unsigned long long u64;

// 4 tensors T_w[10][10], each value duplicated into both f32x2 lanes.
// Layout: g_Tdup[w*100 + p*10 + q]
__device__ u64 g_Tdup[400];

__device__ __forceinline__ u64 ffma2(u64 a, u64 b, u64 c) {
    u64 d;
    asm("fma.rn.f32x2 %0, %1, %2, %3;" : "=l"(d) : "l"(a), "l"(b), "l"(c));
    return d;
}
__device__ __forceinline__ u64 fmul2(u64 a, u64 b) {
    u64 d;
    asm("mul.rn.f32x2 %0, %1, %2;" : "=l"(d) : "l"(a), "l"(b));
    return d;
}
__device__ __forceinline__ u64 pack2(float lo, float hi) {
    u64 d;
    asm("mov.b64 %0, {%1, %2};" : "=l"(d) : "f"(lo), "f"(hi));
    return d;
}
__device__ __forceinline__ void unpack2(u64 v, float& lo, float& hi) {
    asm("mov.b64 {%0, %1}, %2;" : "=f"(lo), "=f"(hi) : "l"(v));
}

// Symmetric-pair index tables: p -> (a, a') with a <= a'
__device__ __constant__ int c_PA[10] = {0,0,0,0,1,1,1,2,2,3};
__device__ __constant__ int c_PB[10] = {0,1,2,3,1,2,3,2,3,3};

// ---------------------------------------------------------------------------
// Prekernel: simulate the params circuit for the 16 basis states -> U, then
// build A_w = Re(U^H Z_w U) and contract to the 4 10x10 tensors T_w.
// ---------------------------------------------------------------------------
__global__ void precompute_T_kernel(const float* __restrict__ params) {
    __shared__ float Ur[DIM][DIM], Ui[DIM][DIM];
    int t = threadIdx.x;

    if (t < DIM) {
        int j = t;
        float2 a[DIM];
#pragma unroll
        for (int k = 0; k < DIM; k++) a[k] = make_float2(k == j ? 1.0f : 0.0f, 0.0f);

        for (int l = 0; l < NL; l++) {
            for (int w = 0; w < NQ; w++) {
                float ty = 0.5f * params[(l * NQ + w) * 2 + 0];
                float sy, cy;
                sincosf(ty, &sy, &cy);
                int m = 1 << (3 - w);
                for (int i = 0; i < DIM; i++) {
                    if (!(i & m)) {
                        float2 a0 = a[i], a1 = a[i | m];
                        a[i]     = make_float2(cy * a0.x - sy * a1.x, cy * a0.y - sy * a1.y);
                        a[i | m] = make_float2(sy * a0.x + cy * a1.x, sy * a0.y + cy * a1.y);
                    }
                }
                float tz = 0.5f * params[(l * NQ + w) * 2 + 1];
                float sz, cz;
                sincosf(tz, &sz, &cz);
                for (int i = 0; i < DIM; i++) {
                    float2 v = a[i];
                    if (i & m) a[i] = make_float2(cz * v.x - sz * v.y, cz * v.y + sz * v.x);
                    else       a[i] = make_float2(cz * v.x + sz * v.y, cz * v.y - sz * v.x);
                }
            }
            for (int w = 0; w < NQ - 1; w++) {
                int mc = 1 << (3 - w);
                int mt = 1 << (2 - w);
                for (int i = 0; i < DIM; i++) {
                    if ((i & mc) && !(i & mt)) {
                        float2 tmp = a[i];
                        a[i] = a[i | mt];
                        a[i | mt] = tmp;
                    }
                }
            }
        }
#pragma unroll
        for (int i = 0; i < DIM; i++) { Ur[i][j] = a[i].x; Ui[i][j] = a[i].y; }
    }
    __syncthreads();

    // A_w(i,j) = sum_k z_w(k) * (Ur[k][i]Ur[k][j] + Ui[k][i]Ui[k][j])
    for (int e = t; e < 400; e += blockDim.x) {
        int w = e / 100;
        int r = e % 100;
        int p = r / 10, q = r % 10;
        int a = c_PA[p], a2 = c_PB[p];
        int b = c_PA[q], b2 = c_PB[q];

        auto Af = [&](int i, int j) {
            float s = 0.0f;
            for (int k = 0; k < DIM; k++) {
                float z = ((k >> (3 - w)) & 1) ? -1.0f : 1.0f;
                s += z * (Ur[k][i] * Ur[k][j] + Ui[k][i] * Ui[k][j]);
            }
            return s;
        };

        float Tv;
        if (a == a2 && b == b2)      Tv = Af(4 * a + b, 4 * a + b);
        else if (a == a2)            Tv = 2.0f * Af(4 * a + b, 4 * a + b2);
        else if (b == b2)            Tv = 2.0f * Af(4 * a + b, 4 * a2 + b);
        else                         Tv = 2.0f * (Af(4 * a + b, 4 * a2 + b2) +
                                                  Af(4 * a + b2, 4 * a2 + b));
        g_Tdup[e] = pack2(Tv, Tv);
    }
}

// ---------------------------------------------------------------------------
// Build the packed (itemX, itemY) outer-product vectors oa[10], ob[10] from
// the two patch float4s.
// ---------------------------------------------------------------------------
__device__ __forceinline__ void build_pair(float4 pX, float4 pY,
                                           u64* __restrict__ oa,
                                           u64* __restrict__ ob) {
    float sX0, cX0, sX1, cX1, sX2, cX2, sX3, cX3;
    float sY0, cY0, sY1, cY1, sY2, cY2, sY3, cY3;
    __sincosf(0.5f * pX.x, &sX0, &cX0);
    __sincosf(0.5f * pX.y, &sX1, &cX1);
    __sincosf(0.5f * pX.z, &sX2, &cX2);
    __sincosf(0.5f * pX.w, &sX3, &cX3);
    __sincosf(0.5f * pY.x, &sY0, &cY0);
    __sincosf(0.5f * pY.y, &sY1, &cY1);
    __sincosf(0.5f * pY.z, &sY2, &cY2);
    __sincosf(0.5f * pY.w, &sY3, &cY3);
    u64 qa2[4], qb2[4];
    qa2[0] = pack2(cX0 * cX1, cY0 * cY1);
    qa2[1] = pack2(cX0 * sX1, cY0 * sY1);
    qa2[2] = pack2(sX0 * cX1, sY0 * cY1);
    qa2[3] = pack2(sX0 * sX1, sY0 * sY1);
    qb2[0] = pack2(cX2 * cX3, cY2 * cY3);
    qb2[1] = pack2(cX2 * sX3, cY2 * sY3);
    qb2[2] = pack2(sX2 * cX3, sY2 * cY3);
    qb2[3] = pack2(sX2 * sX3, sY2 * sY3);
#pragma unroll
    for (int p = 0; p < 10; p++) {
        oa[p] = fmul2(qa2[c_PA[p]], qa2[c_PB[p]]);
        ob[p] = fmul2(qb2[c_PA[p]], qb2[c_PB[p]]);
    }
}

// ---------------------------------------------------------------------------
// Main kernel: FOUR items per thread as two f32x2-packed pairs, so every
// broadcast LDS.128 of a T row-chunk feeds 4 ffma2.
//   ev_w(pair) = sum_p oa_p (x) ( sum_q T_w[p][q] (x) ob_q )
// ---------------------------------------------------------------------------
__global__ __launch_bounds__(256, 2) void vqc_main_kernel(
    const float4* __restrict__ patch, float4* __restrict__ out, int n) {
    __shared__ __align__(16) u64 sT[400];

    int t = threadIdx.x;
    for (int i = t; i < 400; i += 256) sT[i] = g_Tdup[i];
    __syncthreads();

    int base = blockIdx.x * 1024 + t;
    int iA = base, iB = base + 256, iC = base + 512, iD = base + 768;
    bool vA = iA < n, vB = iB < n, vC = iC < n, vD = iD < n;

    float4 pA = patch[vA ? iA : 0];
    float4 pB = patch[vB ? iB : 0];
    float4 pC = patch[vC ? iC : 0];
    float4 pD = patch[vD ? iD : 0];

    u64 oa0[10], ob0[10], oa1[10], ob1[10];
    build_pair(pA, pB, oa0, ob0);   // lanes: (A, B)
    build_pair(pC, pD, oa1, ob1);   // lanes: (C, D)

    const ulonglong2* T2 = reinterpret_cast<const ulonglong2*>(sT);

    u64 ev0[4], ev1[4];
#pragma unroll
    for (int w = 0; w < 4; w++) {
        u64 e0 = 0ull, e1 = 0ull;
#pragma unroll
        for (int p = 0; p < 10; p++) {
            u64 y0 = 0ull, y1 = 0ull;
#pragma unroll
            for (int qq = 0; qq < 5; qq++) {
                ulonglong2 tt = T2[w * 50 + p * 5 + qq];  // broadcast LDS.128
                y0 = ffma2(tt.x, ob0[2 * qq + 0], y0);
                y0 = ffma2(tt.y, ob0[2 * qq + 1], y0);
                y1 = ffma2(tt.x, ob1[2 * qq + 0], y1);
                y1 = ffma2(tt.y, ob1[2 * qq + 1], y1);
            }
            e0 = ffma2(oa0[p], y0, e0);
            e1 = ffma2(oa1[p], y1, e1);
        }
        ev0[w] = e0;
        ev1[w] = e1;
    }

    float r0[4], r1[4], r2[4], r3[4];
#pragma unroll
    for (int w = 0; w < 4; w++) {
        unpack2(ev0[w], r0[w], r1[w]);
        unpack2(ev1[w], r2[w], r3[w]);
    }
    if (vA) out[iA] = make_float4(r0[0], r0[1], r0[2], r0[3]);
    if (vB) out[iB] = make_float4(r1[0], r1[1], r1[2], r1[3]);
    if (vC) out[iC] = make_float4(r2[0], r2[1], r2[2], r2[3]);
    if (vD) out[iD] = make_float4(r3[0], r3[1], r3[2], r3[3]);
}

// ---------------------------------------------------------------------------
extern "C" void kernel_launch(void* const* d_in, const int* in_sizes, int n_in,
                              void* d_out, int out_size) {
    const float* patch  = (const float*)d_in[0];   // (B, 4) float32
    const float* params = (const float*)d_in[1];   // (3, 4, 2) float32
    int n = in_sizes[0] / 4;                       // B

    precompute_T_kernel<<<1, 128>>>(params);

    int blocks = (n + 1023) / 1024;
    vqc_main_kernel<<<blocks, 256>>>(
        (const float4*)patch, (float4*)d_out, n);
}

// round 8
// speedup vs baseline: 1.5368x; 1.3457x over previous
#include <cuda_runtime.h>
#include <cuda_bf16.h>
#include <cstdint>
#include <math.h>

#define NQ 4
#define NL 3
#define DIM 16

// W = [Re U; Im U] (32 rows x 16 cols), bf16 hi/lo split, row-major, packed
// as u32 bf16x2 pairs: g_Wh32[n*8 + c] = {W[n][2c], W[n][2c+1]}.
__device__ uint32_t g_Wh32[32 * 8];
__device__ uint32_t g_Wl32[32 * 8];

// ---------------------------------------------------------------------------
// Prekernel: simulate the params circuit on basis states -> U -> split W.
// ---------------------------------------------------------------------------
__global__ void precompute_W_kernel(const float* __restrict__ params) {
    int j = threadIdx.x;
    if (j >= DIM) return;

    float2 a[DIM];
#pragma unroll
    for (int k = 0; k < DIM; k++) a[k] = make_float2(k == j ? 1.0f : 0.0f, 0.0f);

    for (int l = 0; l < NL; l++) {
        for (int w = 0; w < NQ; w++) {
            float ty = 0.5f * params[(l * NQ + w) * 2 + 0];
            float sy, cy;
            sincosf(ty, &sy, &cy);
            int m = 1 << (3 - w);
            for (int i = 0; i < DIM; i++) {
                if (!(i & m)) {
                    float2 a0 = a[i], a1 = a[i | m];
                    a[i]     = make_float2(cy * a0.x - sy * a1.x, cy * a0.y - sy * a1.y);
                    a[i | m] = make_float2(sy * a0.x + cy * a1.x, sy * a0.y + cy * a1.y);
                }
            }
            float tz = 0.5f * params[(l * NQ + w) * 2 + 1];
            float sz, cz;
            sincosf(tz, &sz, &cz);
            for (int i = 0; i < DIM; i++) {
                float2 v = a[i];
                if (i & m) a[i] = make_float2(cz * v.x - sz * v.y, cz * v.y + sz * v.x);
                else       a[i] = make_float2(cz * v.x + sz * v.y, cz * v.y - sz * v.x);
            }
        }
        for (int w = 0; w < NQ - 1; w++) {
            int mc = 1 << (3 - w);
            int mt = 1 << (2 - w);
            for (int i = 0; i < DIM; i++) {
                if ((i & mc) && !(i & mt)) {
                    float2 tmp = a[i];
                    a[i] = a[i | mt];
                    a[i | mt] = tmp;
                }
            }
        }
    }

    __nv_bfloat16* Wh = reinterpret_cast<__nv_bfloat16*>(g_Wh32);
    __nv_bfloat16* Wl = reinterpret_cast<__nv_bfloat16*>(g_Wl32);
#pragma unroll
    for (int i = 0; i < DIM; i++) {
        float re = a[i].x, im = a[i].y;
        __nv_bfloat16 hr = __float2bfloat16(re);
        __nv_bfloat16 hi = __float2bfloat16(im);
        Wh[i * DIM + j]         = hr;
        Wh[(DIM + i) * DIM + j] = hi;
        Wl[i * DIM + j]         = __float2bfloat16(re - __bfloat162float(hr));
        Wl[(DIM + i) * DIM + j] = __float2bfloat16(im - __bfloat162float(hi));
    }
}

// ---------------------------------------------------------------------------
// HMMA helpers (base-target sm_80+ instructions; no 'a' features)
// ---------------------------------------------------------------------------
__device__ __forceinline__ uint32_t smem_u32(const void* p) {
    uint32_t a;
    asm("{ .reg .u64 t; cvta.to.shared.u64 t, %1; cvt.u32.u64 %0, t; }"
        : "=r"(a) : "l"(p));
    return a;
}

__device__ __forceinline__ void ldmatrix_x4(uint32_t& r0, uint32_t& r1,
                                            uint32_t& r2, uint32_t& r3,
                                            uint32_t addr) {
    asm volatile("ldmatrix.sync.aligned.m8n8.x4.shared.b16 {%0,%1,%2,%3}, [%4];"
                 : "=r"(r0), "=r"(r1), "=r"(r2), "=r"(r3) : "r"(addr));
}

__device__ __forceinline__ void mma_bf16(float* d, uint32_t a0, uint32_t a1,
                                         uint32_t a2, uint32_t a3,
                                         uint32_t b0, uint32_t b1) {
    asm volatile(
        "mma.sync.aligned.m16n8k16.row.col.f32.bf16.bf16.f32 "
        "{%0,%1,%2,%3}, {%4,%5,%6,%7}, {%8,%9}, {%0,%1,%2,%3};"
        : "+f"(d[0]), "+f"(d[1]), "+f"(d[2]), "+f"(d[3])
        : "r"(a0), "r"(a1), "r"(a2), "r"(a3), "r"(b0), "r"(b1));
}

// ---------------------------------------------------------------------------
// Main kernel: each warp handles 32 items. Build s (bf16 hi/lo) -> smem stage
// -> ldmatrix A fragments -> 3 compensated MMAs per N-tile (4 tiles) ->
// epilogue: pr = vr^2+vi^2 local to thread, quad butterfly for ev.
// ---------------------------------------------------------------------------
__global__ __launch_bounds__(256) void vqc_hmma_kernel(
    const float4* __restrict__ patch, float4* __restrict__ out, int n) {
    // per-warp staging: [8 warps][hi/lo][32 rows][8 u32]  (16 KB)
    __shared__ __align__(16) uint32_t stage[8][2][32][8];

    const int tid = threadIdx.x;
    const int wid = tid >> 5;
    const int lane = tid & 31;
    const int g = lane >> 2;      // 0..7
    const int t = lane & 3;       // 0..3

    const int itemBase = blockIdx.x * 256 + wid * 32;
    int myItem = itemBase + lane;
    float4 p = patch[myItem < n ? myItem : (n - 1)];

    // ---- build s[16] and bf16 hi/lo split, write to staging row = lane ----
    {
        float s0, c0, s1, c1, s2, c2, s3, c3;
        __sincosf(0.5f * p.x, &s0, &c0);
        __sincosf(0.5f * p.y, &s1, &c1);
        __sincosf(0.5f * p.z, &s2, &c2);
        __sincosf(0.5f * p.w, &s3, &c3);
        float qa[4] = {c0 * c1, c0 * s1, s0 * c1, s0 * s1};
        float qb[4] = {c2 * c3, c2 * s3, s2 * c3, s2 * s3};

        uint32_t hi[8], lo[8];
#pragma unroll
        for (int c = 0; c < 8; c++) {
            int k0 = 2 * c, k1 = 2 * c + 1;
            float v0 = qa[k0 >> 2] * qb[k0 & 3];
            float v1 = qa[k1 >> 2] * qb[k1 & 3];
            __nv_bfloat16 h0 = __float2bfloat16(v0);
            __nv_bfloat16 h1 = __float2bfloat16(v1);
            __nv_bfloat16 l0 = __float2bfloat16(v0 - __bfloat162float(h0));
            __nv_bfloat16 l1 = __float2bfloat16(v1 - __bfloat162float(h1));
            __nv_bfloat162 hh = __nv_bfloat162(h0, h1);  // low half = even k
            __nv_bfloat162 ll = __nv_bfloat162(l0, l1);
            hi[c] = *reinterpret_cast<uint32_t*>(&hh);
            lo[c] = *reinterpret_cast<uint32_t*>(&ll);
        }
        uint4* dh = reinterpret_cast<uint4*>(&stage[wid][0][lane][0]);
        uint4* dl = reinterpret_cast<uint4*>(&stage[wid][1][lane][0]);
        dh[0] = make_uint4(hi[0], hi[1], hi[2], hi[3]);
        dh[1] = make_uint4(hi[4], hi[5], hi[6], hi[7]);
        dl[0] = make_uint4(lo[0], lo[1], lo[2], lo[3]);
        dl[1] = make_uint4(lo[4], lo[5], lo[6], lo[7]);
    }
    __syncwarp();

    // ---- W (B) fragments, hoisted: b0={W[n][2t],W[n][2t+1]}, b1=k+8 ----
    uint32_t bh[4][2], bl[4][2];
#pragma unroll
    for (int nt = 0; nt < 4; nt++) {
        int idx = (nt * 8 + g) * 8 + t;
        bh[nt][0] = g_Wh32[idx];
        bh[nt][1] = g_Wh32[idx + 4];
        bl[nt][0] = g_Wl32[idx];
        bl[nt][1] = g_Wl32[idx + 4];
    }

    const float s1sgn = (t >= 2) ? -1.0f : 1.0f;   // bit2 of i
    const float s2sgn = (t & 1) ? -1.0f : 1.0f;    // bit1 of i

#pragma unroll
    for (int s = 0; s < 2; s++) {
        // A fragments via ldmatrix.x4 (rows s*16.., 32B rows)
        uint32_t ah0, ah1, ah2, ah3, al0, al1, al2, al3;
        {
            int mrow = s * 16 + (lane & 15);
            int chunk = (lane >> 4);  // 0: cols 0-7 (16B), 1: cols 8-15
            uint32_t addrh = smem_u32(&stage[wid][0][mrow][chunk * 4]);
            uint32_t addrl = smem_u32(&stage[wid][1][mrow][chunk * 4]);
            ldmatrix_x4(ah0, ah1, ah2, ah3, addrh);
            ldmatrix_x4(al0, al1, al2, al3, addrl);
        }

        float acc[4][4];
#pragma unroll
        for (int nt = 0; nt < 4; nt++) {
            acc[nt][0] = acc[nt][1] = acc[nt][2] = acc[nt][3] = 0.0f;
            mma_bf16(acc[nt], ah0, ah1, ah2, ah3, bh[nt][0], bh[nt][1]);
            mma_bf16(acc[nt], ah0, ah1, ah2, ah3, bl[nt][0], bl[nt][1]);
            mma_bf16(acc[nt], al0, al1, al2, al3, bh[nt][0], bh[nt][1]);
        }

        // Epilogue. Thread holds D rows {g, g+8}; per row the 4 basis indices
        // are i in {2t, 2t+1, 8+2t, 9+2t}; vr = tiles 0/1, vi = tiles 2/3.
        float ev[2][4];
#pragma unroll
        for (int r = 0; r < 2; r++) {
            int j0 = 2 * r, j1 = 2 * r + 1;
            float pa = fmaf(acc[0][j0], acc[0][j0], acc[2][j0] * acc[2][j0]); // i=2t
            float pb = fmaf(acc[0][j1], acc[0][j1], acc[2][j1] * acc[2][j1]); // i=2t+1
            float pc = fmaf(acc[1][j0], acc[1][j0], acc[3][j0] * acc[3][j0]); // i=8+2t
            float pd = fmaf(acc[1][j1], acc[1][j1], acc[3][j1] * acc[3][j1]); // i=9+2t
            float S = (pa + pb) + (pc + pd);
            ev[r][0] = (pa + pb) - (pc + pd);  // bit3 of i
            ev[r][1] = s1sgn * S;              // bit2
            ev[r][2] = s2sgn * S;              // bit1
            ev[r][3] = (pa + pc) - (pb + pd);  // bit0
        }

        // quad butterfly (lanes differing in bits 0,1 share the same rows)
#pragma unroll
        for (int r = 0; r < 2; r++) {
#pragma unroll
            for (int w = 0; w < 4; w++) {
                float v = ev[r][w];
                v += __shfl_xor_sync(0xFFFFFFFFu, v, 1);
                v += __shfl_xor_sync(0xFFFFFFFFu, v, 2);
                ev[r][w] = v;
            }
        }

        int item0 = itemBase + s * 16 + g;      // row g
        int item1 = item0 + 8;                  // row g+8
        if (t == 0 && item0 < n)
            out[item0] = make_float4(ev[0][0], ev[0][1], ev[0][2], ev[0][3]);
        if (t == 1 && item1 < n)
            out[item1] = make_float4(ev[1][0], ev[1][1], ev[1][2], ev[1][3]);
    }
}

// ---------------------------------------------------------------------------
extern "C" void kernel_launch(void* const* d_in, const int* in_sizes, int n_in,
                              void* d_out, int out_size) {
    const float* patch  = (const float*)d_in[0];   // (B, 4) float32
    const float* params = (const float*)d_in[1];   // (3, 4, 2) float32
    int n = in_sizes[0] / 4;                       // B

    precompute_W_kernel<<<1, DIM>>>(params);

    int blocks = (n + 255) / 256;
    vqc_hmma_kernel<<<blocks, 256>>>(
        (const float4*)patch, (float4*)d_out, n);
}